// round 7
// baseline (speedup 1.0000x reference)
#include <cuda_runtime.h>
#include <cuda_fp16.h>
#include <cstdint>
#include <cstddef>

#define EPS 0.0001f

// ---------------- static device scratch ----------------
__device__ float g_p2[2048];
__device__ float g_x2[64 * 196];
__device__ __half g_pH[2048 * 512];                    // proto fp16, rows >=2000 zero
__device__ __half g_xTH[(size_t)64 * 224 * 512];       // x^T fp16: [b][n pad224][c], pad rows zero

// ---------------- PTX helpers ----------------
__device__ __forceinline__ uint32_t smem_u32(const void* p) {
    uint32_t a;
    asm("{ .reg .u64 t; cvta.to.shared.u64 t, %1; cvt.u32.u64 %0, t; }" : "=r"(a) : "l"(p));
    return a;
}

__device__ __forceinline__ void cp_async16(uint32_t smem_dst, const void* gmem_src) {
    asm volatile("cp.async.cg.shared.global [%0], [%1], 16;\n"
                 :: "r"(smem_dst), "l"(gmem_src));
}

#define CP_COMMIT() asm volatile("cp.async.commit_group;")
#define CP_WAIT(n)  asm volatile("cp.async.wait_group %0;" :: "n"(n))

#define LDSM_X4(r0, r1, r2, r3, addr) \
    asm volatile("ldmatrix.sync.aligned.m8n8.x4.shared.b16 {%0,%1,%2,%3}, [%4];" \
                 : "=r"(r0), "=r"(r1), "=r"(r2), "=r"(r3) : "r"(addr))

#define LDSM_X2(r0, r1, addr) \
    asm volatile("ldmatrix.sync.aligned.m8n8.x2.shared.b16 {%0,%1}, [%2];" \
                 : "=r"(r0), "=r"(r1) : "r"(addr))

// f16 inputs, f16 accumulators (C/D packed f16x2 pairs)
__device__ __forceinline__ void mma_f16(uint32_t& c0, uint32_t& c1,
                                        const uint32_t* a, const uint32_t* b) {
    asm volatile("mma.sync.aligned.m16n8k16.row.col.f16.f16.f16.f16 "
                 "{%0,%1}, {%2,%3,%4,%5}, {%6,%7}, {%0,%1};"
                 : "+r"(c0), "+r"(c1)
                 : "r"(a[0]), "r"(a[1]), "r"(a[2]), "r"(a[3]),
                   "r"(b[0]), "r"(b[1]));
}

// ---------------- prep kernels ----------------
// p2 + fp16 convert, one warp per prototype row (2048 rows incl. zero pad)
__global__ void proto_prep_kernel(const float* __restrict__ proto) {
    int r = (blockIdx.x * blockDim.x + threadIdx.x) >> 5;
    int lane = threadIdx.x & 31;
    if (r >= 2048) return;
    float s = 0.f;
    if (r < 2000) {
        const float* row = proto + (size_t)r * 512;
        __half* orow = g_pH + (size_t)r * 512;
        #pragma unroll
        for (int it = 0; it < 4; it++) {
            int c = lane * 4 + it * 128;
            float4 v = *(const float4*)(row + c);
            s = fmaf(v.x, v.x, fmaf(v.y, v.y, fmaf(v.z, v.z, fmaf(v.w, v.w, s))));
            __half2 h0 = __floats2half2_rn(v.x, v.y);
            __half2 h1 = __floats2half2_rn(v.z, v.w);
            *(__half2*)(orow + c) = h0;
            *(__half2*)(orow + c + 2) = h1;
        }
        #pragma unroll
        for (int o = 16; o > 0; o >>= 1) s += __shfl_xor_sync(0xffffffffu, s, o);
        if (lane == 0) g_p2[r] = s;
    } else {
        __half2 z = __floats2half2_rn(0.f, 0.f);
        __half* orow = g_pH + (size_t)r * 512;
        #pragma unroll
        for (int it = 0; it < 4; it++) {
            int c = lane * 4 + it * 128;
            *(__half2*)(orow + c) = z;
            *(__half2*)(orow + c + 2) = z;
        }
        if (lane == 0) g_p2[r] = 0.f;
    }
}

__global__ void x2_kernel(const float* __restrict__ x) {
    int t = blockIdx.x * blockDim.x + threadIdx.x;
    if (t >= 64 * 196) return;
    int b = t / 196, n = t % 196;
    const float* base = x + (size_t)b * 512 * 196 + n;
    float s = 0.f;
    #pragma unroll 8
    for (int c = 0; c < 512; c++) { float v = base[c * 196]; s = fmaf(v, v, s); }
    g_x2[t] = s;
}

// transpose+convert x[b][c][n] -> g_xTH[b][n][c] (fp16, n padded to 224, pad rows zero)
__global__ void transpose_h_kernel(const float* __restrict__ x) {
    __shared__ float t[32][33];
    int b = blockIdx.z;
    int n0 = blockIdx.x * 32, c0 = blockIdx.y * 32;
    int tx = threadIdx.x, ty = threadIdx.y;
    const float* xb = x + (size_t)b * 512 * 196;
    #pragma unroll
    for (int i = 0; i < 32; i += 8) {
        int c = c0 + ty + i, n = n0 + tx;
        t[ty + i][tx] = (n < 196) ? xb[(size_t)c * 196 + n] : 0.f;
    }
    __syncthreads();
    __half* ob = g_xTH + (size_t)b * 224 * 512;
    #pragma unroll
    for (int i = 0; i < 32; i += 8) {
        int n = n0 + ty + i, c = c0 + tx;
        ob[(size_t)n * 512 + c] = __float2half(t[tx][ty + i]);
    }
}

// ---------------- main persistent-A fp16 mma kernel ----------------
constexpr int A_STRIDE = 1040;                     // 1024 data + 16 pad
constexpr int A_BYTES = 128 * A_STRIDE;            // 133120
constexpr int B_STRIDE = 80;                       // 64 data + 16 pad
constexpr int B_TILE_BYTES = 224 * B_STRIDE;       // 17920
constexpr int BSTAGES = 3;
constexpr int SMEM_TOTAL = A_BYTES + BSTAGES * B_TILE_BYTES;  // 186880 (known-good footprint)

__global__ void __launch_bounds__(512, 1)
proto_mma_kernel(float* __restrict__ out) {
    extern __shared__ __align__(16) char sm[];
    const uint32_t sbase = smem_u32(sm);
    const uint32_t bbase0 = sbase + A_BYTES;

    const int tid = threadIdx.x;
    const int lane = tid & 31;
    const int warp = tid >> 5;            // 0..15
    const int wm = warp & 3;              // 4 warps over M (32 rows each)
    const int wn = warp >> 2;             // 4 warps over N (56 cols each)
    const int mt = blockIdx.x;            // M-tile 0..15
    const int bg = blockIdx.y;            // batch group 0..7
    const int pm0 = mt * 128;

    // ---- load A tile (128 rows x 512 k fp16 = 64 x 16B chunks per row) once ----
    {
        const __half* gA = g_pH + (size_t)pm0 * 512;
        for (int idx = tid; idx < 8192; idx += 512) {
            int r = idx >> 6, c = idx & 63;
            cp_async16(sbase + r * A_STRIDE + c * 16, gA + (size_t)r * 512 + c * 8);
        }
    }

    // ---- B tile loader ----
    auto loadB = [&](int T) {
        const int slot = T % BSTAGES;
        const int b = bg * 8 + (T >> 4);
        const int kt = T & 15;
        const __half* gB = g_xTH + (size_t)b * 224 * 512 + kt * 32;
        const uint32_t dst = bbase0 + slot * B_TILE_BYTES;
        for (int idx = tid; idx < 896; idx += 512) {
            int r = idx >> 2, c = idx & 3;
            cp_async16(dst + r * B_STRIDE + c * 16, gB + (size_t)r * 512 + c * 8);
        }
    };

    loadB(0); CP_COMMIT();   // group0 = A + B0
    loadB(1); CP_COMMIT();

    // ---- per-thread invariants ----
    float p2v[2][2];
    #pragma unroll
    for (int i = 0; i < 2; i++)
        #pragma unroll
        for (int h = 0; h < 2; h++) {
            int p = pm0 + wm * 32 + i * 16 + (lane >> 2) + h * 8;
            p2v[i][h] = g_p2[p];
        }

    const uint32_t a_l_off = sbase + (wm * 32 + (lane & 15)) * A_STRIDE + (lane >> 4) * 16;
    const uint32_t b_l_off = (wn * 56 + (lane & 7)) * B_STRIDE + ((lane >> 3) & 1) * 16;

    float acc[2][7][4];
    #pragma unroll
    for (int i = 0; i < 2; i++)
        #pragma unroll
        for (int t = 0; t < 7; t++)
            #pragma unroll
            for (int e = 0; e < 4; e++) acc[i][t][e] = 0.f;

    const int NT = 8 * 16;  // 128 tiles
    for (int T = 0; T < NT; T++) {
        CP_WAIT(1);
        __syncthreads();
        if (T + 2 < NT) loadB(T + 2);
        CP_COMMIT();

        const int kt = T & 15;
        const uint32_t abase = a_l_off + kt * 64;
        const uint32_t bbase = bbase0 + (T % BSTAGES) * B_TILE_BYTES + b_l_off;

        // f16 accumulators for this 32-k tile
        uint32_t cacc[2][7][2];
        #pragma unroll
        for (int i = 0; i < 2; i++)
            #pragma unroll
            for (int t = 0; t < 7; t++) { cacc[i][t][0] = 0u; cacc[i][t][1] = 0u; }

        #pragma unroll
        for (int s = 0; s < 2; s++) {          // two k16 steps
            uint32_t afr[2][4];
            LDSM_X4(afr[0][0], afr[0][1], afr[0][2], afr[0][3], abase + s * 32);
            LDSM_X4(afr[1][0], afr[1][1], afr[1][2], afr[1][3], abase + 16 * A_STRIDE + s * 32);
            uint32_t bfr[7][2];
            #pragma unroll
            for (int t = 0; t < 7; t++)
                LDSM_X2(bfr[t][0], bfr[t][1], bbase + t * 8 * B_STRIDE + s * 32);
            #pragma unroll
            for (int i = 0; i < 2; i++)
                #pragma unroll
                for (int t = 0; t < 7; t++)
                    mma_f16(cacc[i][t][0], cacc[i][t][1], afr[i], bfr[t]);
        }

        // promote f16 tile-accumulators into f32 master accumulators
        #pragma unroll
        for (int i = 0; i < 2; i++)
            #pragma unroll
            for (int t = 0; t < 7; t++) {
                float2 lo = __half22float2(*(__half2*)&cacc[i][t][0]);
                float2 hi = __half22float2(*(__half2*)&cacc[i][t][1]);
                acc[i][t][0] += lo.x; acc[i][t][1] += lo.y;
                acc[i][t][2] += hi.x; acc[i][t][3] += hi.y;
            }

        // ---- batch boundary: fused epilogue + accumulator reset ----
        if ((T & 15) == 15) {
            const int b = bg * 8 + (T >> 4);
            const float* x2b = g_x2 + b * 196;
            float* outb = out + (size_t)b * 2000 * 196;
            #pragma unroll
            for (int i = 0; i < 2; i++) {
                #pragma unroll
                for (int h = 0; h < 2; h++) {
                    const int p = pm0 + wm * 32 + i * 16 + (lane >> 2) + h * 8;
                    const bool pok = p < 2000;
                    const float pv = p2v[i][h];
                    float* orow = outb + (size_t)p * 196;
                    #pragma unroll
                    for (int t = 0; t < 7; t++) {
                        const int n = wn * 56 + t * 8 + (lane & 3) * 2;
                        if (pok && n < 196) {
                            float xp0 = acc[i][t][h * 2 + 0];
                            float xp1 = acc[i][t][h * 2 + 1];
                            float d0 = fmaxf(fmaf(-2.f, xp0, x2b[n] + pv), 0.f);
                            float d1 = fmaxf(fmaf(-2.f, xp1, x2b[n + 1] + pv), 0.f);
                            float2 v;
                            v.x = log1pf((1.f - EPS) / (d0 + EPS));
                            v.y = log1pf((1.f - EPS) / (d1 + EPS));
                            *(float2*)(orow + n) = v;
                        }
                    }
                }
            }
            #pragma unroll
            for (int i = 0; i < 2; i++)
                #pragma unroll
                for (int t = 0; t < 7; t++)
                    #pragma unroll
                    for (int e = 0; e < 4; e++) acc[i][t][e] = 0.f;
        }
    }
}

// ---------------- launch (exactly 4 kernels per call) ----------------
extern "C" void kernel_launch(void* const* d_in, const int* in_sizes, int n_in,
                              void* d_out, int out_size) {
    const float* x = (const float*)d_in[0];      // (64, 512, 14, 14)
    const float* proto = (const float*)d_in[1];  // (2000, 512, 1, 1)
    float* out = (float*)d_out;                  // (64, 2000, 14, 14)
    (void)in_sizes; (void)n_in; (void)out_size;

    proto_prep_kernel<<<(2048 * 32 + 255) / 256, 256>>>(proto);
    x2_kernel<<<(64 * 196 + 255) / 256, 256>>>(x);
    transpose_h_kernel<<<dim3(7, 16, 64), dim3(32, 8)>>>(x);

    cudaFuncSetAttribute(proto_mma_kernel,
                         cudaFuncAttributeMaxDynamicSharedMemorySize, SMEM_TOTAL);
    proto_mma_kernel<<<dim3(16, 8), 512, SMEM_TOTAL>>>(out);
}

// round 8
// speedup vs baseline: 1.3789x; 1.3789x over previous
#include <cuda_runtime.h>
#include <cuda_bf16.h>
#include <cstdint>
#include <cstddef>

#define EPS 0.0001f

// ---------------- static device scratch ----------------
__device__ float g_p2[2048];
__device__ float g_x2[64 * 196];
__device__ __nv_bfloat16 g_pB[2048 * 512];                    // proto bf16, rows >=2000 zero
__device__ __nv_bfloat16 g_xTB[(size_t)64 * 224 * 512];       // x^T bf16: [b][n pad224][c], pad rows zero

// ---------------- PTX helpers ----------------
__device__ __forceinline__ uint32_t smem_u32(const void* p) {
    uint32_t a;
    asm("{ .reg .u64 t; cvta.to.shared.u64 t, %1; cvt.u32.u64 %0, t; }" : "=r"(a) : "l"(p));
    return a;
}

__device__ __forceinline__ void cp_async16(uint32_t smem_dst, const void* gmem_src) {
    asm volatile("cp.async.cg.shared.global [%0], [%1], 16;\n"
                 :: "r"(smem_dst), "l"(gmem_src));
}

#define CP_COMMIT() asm volatile("cp.async.commit_group;")
#define CP_WAIT(n)  asm volatile("cp.async.wait_group %0;" :: "n"(n))

#define LDSM_X4(r0, r1, r2, r3, addr) \
    asm volatile("ldmatrix.sync.aligned.m8n8.x4.shared.b16 {%0,%1,%2,%3}, [%4];" \
                 : "=r"(r0), "=r"(r1), "=r"(r2), "=r"(r3) : "r"(addr))

#define LDSM_X2(r0, r1, addr) \
    asm volatile("ldmatrix.sync.aligned.m8n8.x2.shared.b16 {%0,%1}, [%2];" \
                 : "=r"(r0), "=r"(r1) : "r"(addr))

__device__ __forceinline__ void mma_bf16(float* c, const uint32_t* a, const uint32_t* b) {
    asm volatile("mma.sync.aligned.m16n8k16.row.col.f32.bf16.bf16.f32 "
                 "{%0,%1,%2,%3}, {%4,%5,%6,%7}, {%8,%9}, {%0,%1,%2,%3};"
                 : "+f"(c[0]), "+f"(c[1]), "+f"(c[2]), "+f"(c[3])
                 : "r"(a[0]), "r"(a[1]), "r"(a[2]), "r"(a[3]),
                   "r"(b[0]), "r"(b[1]));
}

// activation: log((d+1)/(d+eps)) = log1p(u), u = (1-eps)/(d+eps)
__device__ __forceinline__ float act_fn(float d) {
    float u = __fdividef(1.f - EPS, d + EPS);
    if (u < 0.0625f)
        return u * fmaf(u, fmaf(u, fmaf(u, -0.25f, 0.33333333f), -0.5f), 1.f);
    return __logf(1.f + u);
}

// ---------------- prep kernels ----------------
// p2 + bf16 convert, one warp per prototype row (2048 rows incl. zero pad)
__global__ void proto_prep_kernel(const float* __restrict__ proto) {
    int r = (blockIdx.x * blockDim.x + threadIdx.x) >> 5;
    int lane = threadIdx.x & 31;
    if (r >= 2048) return;
    if (r < 2000) {
        const float* row = proto + (size_t)r * 512;
        __nv_bfloat16* orow = g_pB + (size_t)r * 512;
        float s = 0.f;
        #pragma unroll
        for (int it = 0; it < 4; it++) {
            int c = lane * 4 + it * 128;
            float4 v = *(const float4*)(row + c);
            s = fmaf(v.x, v.x, fmaf(v.y, v.y, fmaf(v.z, v.z, fmaf(v.w, v.w, s))));
            *(__nv_bfloat162*)(orow + c)     = __floats2bfloat162_rn(v.x, v.y);
            *(__nv_bfloat162*)(orow + c + 2) = __floats2bfloat162_rn(v.z, v.w);
        }
        #pragma unroll
        for (int o = 16; o > 0; o >>= 1) s += __shfl_xor_sync(0xffffffffu, s, o);
        if (lane == 0) g_p2[r] = s;
    } else {
        __nv_bfloat162 z = __floats2bfloat162_rn(0.f, 0.f);
        __nv_bfloat16* orow = g_pB + (size_t)r * 512;
        #pragma unroll
        for (int it = 0; it < 4; it++) {
            int c = lane * 4 + it * 128;
            *(__nv_bfloat162*)(orow + c)     = z;
            *(__nv_bfloat162*)(orow + c + 2) = z;
        }
        if (lane == 0) g_p2[r] = 0.f;
    }
}

__global__ void x2_kernel(const float* __restrict__ x) {
    int t = blockIdx.x * blockDim.x + threadIdx.x;
    if (t >= 64 * 196) return;
    int b = t / 196, n = t % 196;
    const float* base = x + (size_t)b * 512 * 196 + n;
    float s = 0.f;
    #pragma unroll 8
    for (int c = 0; c < 512; c++) { float v = base[c * 196]; s = fmaf(v, v, s); }
    g_x2[t] = s;
}

// transpose+convert x[b][c][n] -> g_xTB[b][n][c] (bf16, n padded to 224, pad rows zero)
__global__ void transpose_bf_kernel(const float* __restrict__ x) {
    __shared__ float t[32][33];
    int b = blockIdx.z;
    int n0 = blockIdx.x * 32, c0 = blockIdx.y * 32;
    int tx = threadIdx.x, ty = threadIdx.y;
    const float* xb = x + (size_t)b * 512 * 196;
    #pragma unroll
    for (int i = 0; i < 32; i += 8) {
        int c = c0 + ty + i, n = n0 + tx;
        t[ty + i][tx] = (n < 196) ? xb[(size_t)c * 196 + n] : 0.f;
    }
    __syncthreads();
    __nv_bfloat16* ob = g_xTB + (size_t)b * 224 * 512;
    #pragma unroll
    for (int i = 0; i < 32; i += 8) {
        int n = n0 + ty + i, c = c0 + tx;
        ob[(size_t)n * 512 + c] = __float2bfloat16(t[tx][ty + i]);
    }
}

// ---------------- main streamed bf16 mma kernel (2 CTAs/SM) ----------------
// CTA: M=64 protos x N=224 pixels x one batch; K=512 in 16 chunks of 32.
// 256 threads = 8 warps: wm = warp&1 (M 32 rows), wn = warp>>1 (N 56 cols).
// 4-stage cp.async pipeline streaming A(64x32) + B(224x32) per k-chunk.

constexpr int A_ST = 80;                            // 64B data + 16 pad
constexpr int B_ST = 80;
constexpr int A_TILE_BYTES = 64 * A_ST;             // 5120
constexpr int B_TILE_BYTES = 224 * B_ST;            // 17920
constexpr int STAGE_BYTES = A_TILE_BYTES + B_TILE_BYTES;  // 23040
constexpr int BSTAGES = 4;
constexpr int SMEM_TOTAL = BSTAGES * STAGE_BYTES;   // 92160 -> 2 CTAs/SM

__global__ void __launch_bounds__(256, 2)
proto_mma_kernel(float* __restrict__ out) {
    extern __shared__ __align__(16) char sm[];
    const uint32_t sbase = smem_u32(sm);

    const int tid = threadIdx.x;
    const int lane = tid & 31;
    const int warp = tid >> 5;            // 0..7
    const int wm = warp & 1;              // 2 warps over M (32 rows each)
    const int wn = warp >> 1;             // 4 warps over N (56 cols each)
    const int mt = blockIdx.x;            // M-tile 0..31
    const int b = blockIdx.y;             // batch 0..63
    const int pm0 = mt * 64;

    const __nv_bfloat16* gA = g_pB + (size_t)pm0 * 512;
    const __nv_bfloat16* xTb = g_xTB + (size_t)b * 224 * 512;

    // ---- stage loader: A (64 rows x 4 chunks) + B (224 rows x 4 chunks) ----
    auto load_stage = [&](int kt, int slot) {
        const uint32_t dst = sbase + slot * STAGE_BYTES;
        {   // A: 256 chunks, exactly one per thread
            int r = tid >> 2, c = tid & 3;
            cp_async16(dst + r * A_ST + c * 16, gA + (size_t)r * 512 + kt * 32 + c * 8);
        }
        // B: 896 chunks
        for (int idx = tid; idx < 896; idx += 256) {
            int r = idx >> 2, c = idx & 3;
            cp_async16(dst + A_TILE_BYTES + r * B_ST + c * 16,
                       xTb + (size_t)r * 512 + kt * 32 + c * 8);
        }
    };

    load_stage(0, 0); CP_COMMIT();
    load_stage(1, 1); CP_COMMIT();
    load_stage(2, 2); CP_COMMIT();

    const uint32_t a_l_off = (wm * 32 + (lane & 15)) * A_ST + (lane >> 4) * 16;
    const uint32_t b_l_off = A_TILE_BYTES + (wn * 56 + (lane & 7)) * B_ST + ((lane >> 3) & 1) * 16;

    float acc[2][7][4];
    #pragma unroll
    for (int i = 0; i < 2; i++)
        #pragma unroll
        for (int t = 0; t < 7; t++)
            #pragma unroll
            for (int e = 0; e < 4; e++) acc[i][t][e] = 0.f;

    for (int kt = 0; kt < 16; kt++) {
        CP_WAIT(2);
        __syncthreads();
        if (kt + 3 < 16) load_stage(kt + 3, (kt + 3) & 3);
        CP_COMMIT();

        const uint32_t st = sbase + (kt & 3) * STAGE_BYTES;
        const uint32_t abase = st + a_l_off;
        const uint32_t bbase = st + b_l_off;

        #pragma unroll
        for (int s = 0; s < 2; s++) {          // two k16 steps per 32-k chunk
            uint32_t afr[2][4];
            LDSM_X4(afr[0][0], afr[0][1], afr[0][2], afr[0][3], abase + s * 32);
            LDSM_X4(afr[1][0], afr[1][1], afr[1][2], afr[1][3], abase + 16 * A_ST + s * 32);
            uint32_t bfr[7][2];
            #pragma unroll
            for (int t = 0; t < 7; t++)
                LDSM_X2(bfr[t][0], bfr[t][1], bbase + t * 8 * B_ST + s * 32);
            #pragma unroll
            for (int i = 0; i < 2; i++)
                #pragma unroll
                for (int t = 0; t < 7; t++)
                    mma_bf16(acc[i][t], afr[i], bfr[t]);
        }
    }

    // ---- fused epilogue ----
    const float* x2b = g_x2 + b * 196;
    float* outb = out + (size_t)b * 2000 * 196;
    #pragma unroll
    for (int i = 0; i < 2; i++) {
        #pragma unroll
        for (int h = 0; h < 2; h++) {
            const int p = pm0 + wm * 32 + i * 16 + (lane >> 2) + h * 8;
            if (p >= 2000) continue;
            const float pv = g_p2[p];
            float* orow = outb + (size_t)p * 196;
            #pragma unroll
            for (int t = 0; t < 7; t++) {
                const int n = wn * 56 + t * 8 + (lane & 3) * 2;
                if (n < 196) {
                    float d0 = fmaxf(fmaf(-2.f, acc[i][t][h * 2 + 0], x2b[n] + pv), 0.f);
                    float d1 = fmaxf(fmaf(-2.f, acc[i][t][h * 2 + 1], x2b[n + 1] + pv), 0.f);
                    float2 v;
                    v.x = act_fn(d0);
                    v.y = act_fn(d1);
                    *(float2*)(orow + n) = v;
                }
            }
        }
    }
}

// ---------------- launch (exactly 4 kernels per call) ----------------
extern "C" void kernel_launch(void* const* d_in, const int* in_sizes, int n_in,
                              void* d_out, int out_size) {
    const float* x = (const float*)d_in[0];      // (64, 512, 14, 14)
    const float* proto = (const float*)d_in[1];  // (2000, 512, 1, 1)
    float* out = (float*)d_out;                  // (64, 2000, 14, 14)
    (void)in_sizes; (void)n_in; (void)out_size;

    proto_prep_kernel<<<(2048 * 32 + 255) / 256, 256>>>(proto);
    x2_kernel<<<(64 * 196 + 255) / 256, 256>>>(x);
    transpose_bf_kernel<<<dim3(7, 16, 64), dim3(32, 8)>>>(x);

    cudaFuncSetAttribute(proto_mma_kernel,
                         cudaFuncAttributeMaxDynamicSharedMemorySize, SMEM_TOTAL);
    proto_mma_kernel<<<dim3(32, 64), 256, SMEM_TOTAL>>>(out);
}

// round 10
// speedup vs baseline: 1.6957x; 1.2297x over previous
#include <cuda_runtime.h>
#include <cuda_bf16.h>
#include <cstdint>
#include <cstddef>

#define EPS 0.0001f

// ---------------- static device scratch ----------------
__device__ float g_p2[2048];
__device__ float g_x2[64 * 196];
__device__ __nv_bfloat16 g_pB[2048 * 512];                    // proto bf16, rows >=2000 zero
__device__ __nv_bfloat16 g_xTB[(size_t)64 * 224 * 512];       // x^T bf16: [b][n pad224][c], pad rows zero

// ---------------- PTX helpers ----------------
__device__ __forceinline__ uint32_t smem_u32(const void* p) {
    uint32_t a;
    asm("{ .reg .u64 t; cvta.to.shared.u64 t, %1; cvt.u32.u64 %0, t; }" : "=r"(a) : "l"(p));
    return a;
}

__device__ __forceinline__ void cp_async16(uint32_t smem_dst, const void* gmem_src) {
    asm volatile("cp.async.cg.shared.global [%0], [%1], 16;\n"
                 :: "r"(smem_dst), "l"(gmem_src));
}

#define CP_COMMIT() asm volatile("cp.async.commit_group;")
#define CP_WAIT(n)  asm volatile("cp.async.wait_group %0;" :: "n"(n))

#define LDSM_X4(r0, r1, r2, r3, addr) \
    asm volatile("ldmatrix.sync.aligned.m8n8.x4.shared.b16 {%0,%1,%2,%3}, [%4];" \
                 : "=r"(r0), "=r"(r1), "=r"(r2), "=r"(r3) : "r"(addr))

#define LDSM_X2(r0, r1, addr) \
    asm volatile("ldmatrix.sync.aligned.m8n8.x2.shared.b16 {%0,%1}, [%2];" \
                 : "=r"(r0), "=r"(r1) : "r"(addr))

__device__ __forceinline__ void mma_bf16(float* c, const uint32_t* a, const uint32_t* b) {
    asm volatile("mma.sync.aligned.m16n8k16.row.col.f32.bf16.bf16.f32 "
                 "{%0,%1,%2,%3}, {%4,%5,%6,%7}, {%8,%9}, {%0,%1,%2,%3};"
                 : "+f"(c[0]), "+f"(c[1]), "+f"(c[2]), "+f"(c[3])
                 : "r"(a[0]), "r"(a[1]), "r"(a[2]), "r"(a[3]),
                   "r"(b[0]), "r"(b[1]));
}

// activation: log((d+1)/(d+eps)) = log1p(u), u = (1-eps)/(d+eps)
__device__ __forceinline__ float act_fn(float d) {
    float u = __fdividef(1.f - EPS, d + EPS);
    if (u < 0.0625f)
        return u * fmaf(u, fmaf(u, fmaf(u, -0.25f, 0.33333333f), -0.5f), 1.f);
    return __logf(1.f + u);
}

// ---------------- prep kernels ----------------
// p2 + bf16 convert (one warp per row) + zero g_x2 for the transpose's atomics
__global__ void proto_prep_kernel(const float* __restrict__ proto) {
    int gt = blockIdx.x * blockDim.x + threadIdx.x;
    if (gt < 64 * 196) g_x2[gt] = 0.f;

    int r = gt >> 5;
    int lane = threadIdx.x & 31;
    if (r >= 2048) return;
    if (r < 2000) {
        const float* row = proto + (size_t)r * 512;
        __nv_bfloat16* orow = g_pB + (size_t)r * 512;
        float s = 0.f;
        #pragma unroll
        for (int it = 0; it < 4; it++) {
            int c = lane * 4 + it * 128;
            float4 v = *(const float4*)(row + c);
            s = fmaf(v.x, v.x, fmaf(v.y, v.y, fmaf(v.z, v.z, fmaf(v.w, v.w, s))));
            *(__nv_bfloat162*)(orow + c)     = __floats2bfloat162_rn(v.x, v.y);
            *(__nv_bfloat162*)(orow + c + 2) = __floats2bfloat162_rn(v.z, v.w);
        }
        #pragma unroll
        for (int o = 16; o > 0; o >>= 1) s += __shfl_xor_sync(0xffffffffu, s, o);
        if (lane == 0) g_p2[r] = s;
    } else {
        __nv_bfloat162 z = __floats2bfloat162_rn(0.f, 0.f);
        __nv_bfloat16* orow = g_pB + (size_t)r * 512;
        #pragma unroll
        for (int it = 0; it < 4; it++) {
            int c = lane * 4 + it * 128;
            *(__nv_bfloat162*)(orow + c)     = z;
            *(__nv_bfloat162*)(orow + c + 2) = z;
        }
        if (lane == 0) g_p2[r] = 0.f;
    }
}

// transpose+convert x[b][c][n] -> g_xTB[b][n][c] (bf16, n pad 224, pad rows zero)
// AND accumulate x2[b][n] += sum_c x^2 over this tile's 32 c-values.
__global__ void transpose_bf_kernel(const float* __restrict__ x) {
    __shared__ float t[32][33];
    __shared__ float s_ssq[32];
    int b = blockIdx.z;
    int n0 = blockIdx.x * 32, c0 = blockIdx.y * 32;
    int tx = threadIdx.x, ty = threadIdx.y;
    int tid = ty * 32 + tx;
    if (tid < 32) s_ssq[tid] = 0.f;
    const float* xb = x + (size_t)b * 512 * 196;
    float part = 0.f;
    #pragma unroll
    for (int i = 0; i < 32; i += 8) {
        int c = c0 + ty + i, n = n0 + tx;
        float v = (n < 196) ? xb[(size_t)c * 196 + n] : 0.f;
        t[ty + i][tx] = v;
        part = fmaf(v, v, part);
    }
    __syncthreads();
    atomicAdd(&s_ssq[tx], part);          // partial ssq for n = n0+tx
    __nv_bfloat16* ob = g_xTB + (size_t)b * 224 * 512;
    #pragma unroll
    for (int i = 0; i < 32; i += 8) {
        int n = n0 + ty + i, c = c0 + tx;
        ob[(size_t)n * 512 + c] = __float2bfloat16(t[tx][ty + i]);
    }
    __syncthreads();
    if (ty == 0 && n0 + tx < 196) atomicAdd(&g_x2[b * 196 + n0 + tx], s_ssq[tx]);
}

// ---------------- main streamed bf16 mma kernel (2 CTAs/SM) ----------------
constexpr int A_ST = 80;                            // 64B data + 16 pad
constexpr int B_ST = 80;
constexpr int A_TILE_BYTES = 64 * A_ST;             // 5120
constexpr int B_TILE_BYTES = 224 * B_ST;            // 17920
constexpr int STAGE_BYTES = A_TILE_BYTES + B_TILE_BYTES;  // 23040
constexpr int BSTAGES = 4;
constexpr int SMEM_TOTAL = BSTAGES * STAGE_BYTES;   // 92160 -> 2 CTAs/SM

__global__ void __launch_bounds__(256, 2)
proto_mma_kernel(float* __restrict__ out) {
    extern __shared__ __align__(16) char sm[];
    const uint32_t sbase = smem_u32(sm);

    const int tid = threadIdx.x;
    const int lane = tid & 31;
    const int warp = tid >> 5;            // 0..7
    const int wm = warp & 1;              // 2 warps over M (32 rows each)
    const int wn = warp >> 1;             // 4 warps over N (56 cols each)
    const int mt = blockIdx.x;            // M-tile 0..31
    const int b = blockIdx.y;             // batch 0..63
    const int pm0 = mt * 64;

    const __nv_bfloat16* gA = g_pB + (size_t)pm0 * 512;
    const __nv_bfloat16* xTb = g_xTB + (size_t)b * 224 * 512;

    auto load_stage = [&](int kt, int slot) {
        const uint32_t dst = sbase + slot * STAGE_BYTES;
        {   // A: 256 chunks, one per thread
            int r = tid >> 2, c = tid & 3;
            cp_async16(dst + r * A_ST + c * 16, gA + (size_t)r * 512 + kt * 32 + c * 8);
        }
        for (int idx = tid; idx < 896; idx += 256) {
            int r = idx >> 2, c = idx & 3;
            cp_async16(dst + A_TILE_BYTES + r * B_ST + c * 16,
                       xTb + (size_t)r * 512 + kt * 32 + c * 8);
        }
    };

    load_stage(0, 0); CP_COMMIT();
    load_stage(1, 1); CP_COMMIT();
    load_stage(2, 2); CP_COMMIT();

    // per-thread smem fragment addresses
    const uint32_t a_l_off = (wm * 32 + (lane & 15)) * A_ST + (lane >> 4) * 16;
    // X2 base: lanes 0-15 address 8 rows x 2 halves
    const uint32_t b_l2_off = A_TILE_BYTES + (wn * 56 + (lane & 7)) * B_ST + ((lane >> 3) & 1) * 16;
    // X4 base: lanes 16-31 address the next 8-row n-group
    const uint32_t b_l4_off = A_TILE_BYTES
        + (wn * 56 + (lane >> 4) * 8 + (lane & 7)) * B_ST + ((lane >> 3) & 1) * 16;

    // prefetch p2 for this thread's 4 output rows
    float p2r[2][2];
    #pragma unroll
    for (int i = 0; i < 2; i++)
        #pragma unroll
        for (int h = 0; h < 2; h++) {
            int p = pm0 + wm * 32 + i * 16 + (lane >> 2) + h * 8;
            p2r[i][h] = g_p2[p];          // rows >=2000 read zero-pad region (p<2048)
        }

    float acc[2][7][4];
    #pragma unroll
    for (int i = 0; i < 2; i++)
        #pragma unroll
        for (int t = 0; t < 7; t++)
            #pragma unroll
            for (int e = 0; e < 4; e++) acc[i][t][e] = 0.f;

    for (int kt = 0; kt < 16; kt++) {
        CP_WAIT(2);
        __syncthreads();
        if (kt + 3 < 16) load_stage(kt + 3, (kt + 3) & 3);
        CP_COMMIT();

        const uint32_t st = sbase + (kt & 3) * STAGE_BYTES;
        const uint32_t abase = st + a_l_off;
        const uint32_t b4 = st + b_l4_off;
        const uint32_t b2 = st + b_l2_off;

        #pragma unroll
        for (int s = 0; s < 2; s++) {          // two k16 steps per 32-k chunk
            uint32_t afr[2][4];
            LDSM_X4(afr[0][0], afr[0][1], afr[0][2], afr[0][3], abase + s * 32);
            LDSM_X4(afr[1][0], afr[1][1], afr[1][2], afr[1][3], abase + 16 * A_ST + s * 32);
            uint32_t bfr[7][2];
            LDSM_X4(bfr[0][0], bfr[0][1], bfr[1][0], bfr[1][1], b4 + 0 * 16 * B_ST + s * 32);
            LDSM_X4(bfr[2][0], bfr[2][1], bfr[3][0], bfr[3][1], b4 + 1 * 16 * B_ST + s * 32);
            LDSM_X4(bfr[4][0], bfr[4][1], bfr[5][0], bfr[5][1], b4 + 2 * 16 * B_ST + s * 32);
            LDSM_X2(bfr[6][0], bfr[6][1], b2 + 6 * 8 * B_ST + s * 32);
            #pragma unroll
            for (int i = 0; i < 2; i++)
                #pragma unroll
                for (int t = 0; t < 7; t++)
                    mma_bf16(acc[i][t], afr[i], bfr[t]);
        }
    }

    // ---- fused epilogue ----
    const float* x2b = g_x2 + b * 196;
    float* outb = out + (size_t)b * 2000 * 196;
    #pragma unroll
    for (int i = 0; i < 2; i++) {
        #pragma unroll
        for (int h = 0; h < 2; h++) {
            const int p = pm0 + wm * 32 + i * 16 + (lane >> 2) + h * 8;
            if (p >= 2000) continue;
            const float pv = p2r[i][h];
            float* orow = outb + (size_t)p * 196;
            #pragma unroll
            for (int t = 0; t < 7; t++) {
                const int n = wn * 56 + t * 8 + (lane & 3) * 2;
                if (n < 196) {
                    float d0 = fmaxf(fmaf(-2.f, acc[i][t][h * 2 + 0], x2b[n] + pv), 0.f);
                    float d1 = fmaxf(fmaf(-2.f, acc[i][t][h * 2 + 1], x2b[n + 1] + pv), 0.f);
                    float2 v;
                    v.x = act_fn(d0);
                    v.y = act_fn(d1);
                    *(float2*)(orow + n) = v;
                }
            }
        }
    }
}

// ---------------- launch (3 kernels per call) ----------------
extern "C" void kernel_launch(void* const* d_in, const int* in_sizes, int n_in,
                              void* d_out, int out_size) {
    const float* x = (const float*)d_in[0];      // (64, 512, 14, 14)
    const float* proto = (const float*)d_in[1];  // (2000, 512, 1, 1)
    float* out = (float*)d_out;                  // (64, 2000, 14, 14)
    (void)in_sizes; (void)n_in; (void)out_size;

    proto_prep_kernel<<<(2048 * 32 + 255) / 256, 256>>>(proto);
    transpose_bf_kernel<<<dim3(7, 16, 64), dim3(32, 8)>>>(x);

    cudaFuncSetAttribute(proto_mma_kernel,
                         cudaFuncAttributeMaxDynamicSharedMemorySize, SMEM_TOTAL);
    proto_mma_kernel<<<dim3(32, 64), 256, SMEM_TOTAL>>>(out);
}